// round 1
// baseline (speedup 1.0000x reference)
#include <cuda_runtime.h>
#include <math_constants.h>

#define NN 512
#define DIMX 256
#define NH 8
#define DH 64
#define INNER 512
#define NR 66
#define PI_F 3.14159265358979f
#define SCALE_F 0.125f          // 64^-0.5
#define INV_NORM (1.0f/51.0f)
#define DSTEP_F (7.0f*PI_F/15.0f)

// ---------------- scratch (static device allocations) ----------------
__device__ float g_q [NN*INNER];
__device__ float g_kc[NN*INNER];
__device__ float g_v [NN*INNER];
__device__ float g_P [NN*NR*NH];          // [i][r][h]  (transposed for float4 broadcast)
__device__ float g_sc[(size_t)NH*NN*NN];  // scores -> attn (8 MB)
__device__ float g_ao[NN*INNER];          // attention output before Wo

// ---------------- K1: fused QKV projections (x @ W) -------------------
// grid (8 ntile, 8 mtile, 3), block 256.  M=512, N=512, K=256
__global__ void qkv_kernel(const float* __restrict__ x,
                           const float* __restrict__ Wq,
                           const float* __restrict__ Wk,
                           const float* __restrict__ Wv) {
    __shared__ float As[16][64];   // [k][m]
    __shared__ float Bs[16][64];   // [k][n]
    const float* W = (blockIdx.z == 0) ? Wq : ((blockIdx.z == 1) ? Wk : Wv);
    float* out = (blockIdx.z == 0) ? g_q : ((blockIdx.z == 1) ? g_kc : g_v);
    const int n0 = blockIdx.x * 64, m0 = blockIdx.y * 64;
    const int tid = threadIdx.x;
    const int tx = tid & 15, ty = tid >> 4;

    float acc[4][4] = {};
    for (int k0 = 0; k0 < DIMX; k0 += 16) {
#pragma unroll
        for (int t = 0; t < 4; t++) {
            int idx = tid + t * 256;
            int m = idx >> 4, k = idx & 15;
            As[k][m] = x[(m0 + m) * DIMX + k0 + k];
        }
#pragma unroll
        for (int t = 0; t < 4; t++) {
            int idx = tid + t * 256;
            int k = idx >> 6, n = idx & 63;
            Bs[k][n] = W[(k0 + k) * INNER + n0 + n];
        }
        __syncthreads();
#pragma unroll
        for (int kk = 0; kk < 16; kk++) {
            float4 a = *reinterpret_cast<const float4*>(&As[kk][ty * 4]);
            float4 b = *reinterpret_cast<const float4*>(&Bs[kk][tx * 4]);
            float av[4] = {a.x, a.y, a.z, a.w};
            float bv[4] = {b.x, b.y, b.z, b.w};
#pragma unroll
            for (int i = 0; i < 4; i++)
#pragma unroll
                for (int j = 0; j < 4; j++) acc[i][j] += av[i] * bv[j];
        }
        __syncthreads();
    }
#pragma unroll
    for (int i = 0; i < 4; i++) {
        float4 r = make_float4(acc[i][0], acc[i][1], acc[i][2], acc[i][3]);
        *reinterpret_cast<float4*>(&out[(m0 + ty * 4 + i) * INNER + n0 + tx * 4]) = r;
    }
}

// ---------------- K2: P[i][r][h] = sum_d q[i,h*64+d] * Wk_r[r, h*64+d] --
// grid (512), block 256
__global__ void p_kernel(const float* __restrict__ Wk) {
    const float* Wr = Wk + (size_t)DIMX * INNER;   // rows 256..321
    const int i = blockIdx.x;
    __shared__ float qs[INNER];
    const int tid = threadIdx.x;
    qs[tid]       = g_q[i * INNER + tid];
    qs[tid + 256] = g_q[i * INNER + tid + 256];
    __syncthreads();
    for (int t = tid; t < NH * NR; t += 256) {
        int h = t / NR, r = t % NR;
        const float4* w  = reinterpret_cast<const float4*>(Wr + (size_t)r * INNER + h * DH);
        const float4* qq = reinterpret_cast<const float4*>(qs + h * DH);
        float acc = 0.f;
#pragma unroll
        for (int u = 0; u < 16; u++) {
            float4 wv = w[u];
            float4 qv = qq[u];
            acc += wv.x * qv.x + wv.y * qv.y + wv.z * qv.z + wv.w * qv.w;
        }
        g_P[((size_t)i * NR + r) * NH + h] = acc;  // transposed layout [i][r][h]
    }
}

// ---------------- K3: content scores  S[h,i,j] = scale * q_h[i] . kc_h[j] --
// grid (8 jtile, 8 itile, 8 h), block 256
__global__ void cs_kernel() {
    const int h = blockIdx.z;
    const int j0 = blockIdx.x * 64, i0 = blockIdx.y * 64;
    __shared__ float Qs[64][65];
    __shared__ float Ks[64][65];
    const int tid = threadIdx.x, tx = tid & 15, ty = tid >> 4;
#pragma unroll
    for (int t = 0; t < 16; t++) {
        int idx = tid + t * 256;
        int row = idx >> 6, d = idx & 63;
        Qs[row][d] = g_q [(i0 + row) * INNER + h * DH + d];
        Ks[row][d] = g_kc[(j0 + row) * INNER + h * DH + d];
    }
    __syncthreads();
    float acc[4][4] = {};
#pragma unroll 8
    for (int d = 0; d < 64; d++) {
        float a[4], b[4];
#pragma unroll
        for (int m = 0; m < 4; m++) a[m] = Qs[ty * 4 + m][d];
#pragma unroll
        for (int n = 0; n < 4; n++) b[n] = Ks[tx * 4 + n][d];
#pragma unroll
        for (int m = 0; m < 4; m++)
#pragma unroll
            for (int n = 0; n < 4; n++) acc[m][n] += a[m] * b[n];
    }
#pragma unroll
    for (int m = 0; m < 4; m++) {
        int i = i0 + ty * 4 + m;
        float4 r = make_float4(acc[m][0] * SCALE_F, acc[m][1] * SCALE_F,
                               acc[m][2] * SCALE_F, acc[m][3] * SCALE_F);
        *reinterpret_cast<float4*>(&g_sc[((size_t)h * NN + i) * NN + j0 + tx * 4]) = r;
    }
}

// ---------------- K4: RPE features + score add + softmax --------------
// grid (512 = one per query i), block 256
__global__ void rpe_softmax_kernel(const float* __restrict__ pos) {
    const int i = blockIdx.x;
    __shared__ float Ps[NR * NH];     // [r][h]
    __shared__ float s_s[NH][NN];
    const int tid = threadIdx.x;
    for (int t = tid; t < NR * NH; t += 256) Ps[t] = g_P[(size_t)i * NR * NH + t];
    __syncthreads();

    const float2* pos2 = reinterpret_cast<const float2*>(pos);
    const float2 pq = pos2[i];
    const float4* Pt4 = reinterpret_cast<const float4*>(Ps);

#pragma unroll
    for (int jj = 0; jj < 2; jj++) {
        const int j = tid + jj * 256;
        const float2 pk = pos2[j];
        float dx = (pk.x - pq.x) * INV_NORM;
        dx = __fdividef(dx, 1.0f + fabsf(dx));
        float dy = (pk.y - pq.y) * INV_NORM;
        dy = __fdividef(dy, 1.0f + fabsf(dy));

        float f[NR];
        // x-axis fourier bands via angle-addition recurrence
        {
            float s, c, sd, cd;
            __sincosf(dx * PI_F, &s, &c);
            __sincosf(dx * DSTEP_F, &sd, &cd);
#pragma unroll
            for (int k = 0; k < 16; k++) {
                f[k] = s; f[16 + k] = c;
                float ns = s * cd + c * sd;
                float nc = c * cd - s * sd;
                s = ns; c = nc;
            }
            f[32] = dx;
        }
        {
            float s, c, sd, cd;
            __sincosf(dy * PI_F, &s, &c);
            __sincosf(dy * DSTEP_F, &sd, &cd);
#pragma unroll
            for (int k = 0; k < 16; k++) {
                f[33 + k] = s; f[49 + k] = c;
                float ns = s * cd + c * sd;
                float nc = c * cd - s * sd;
                s = ns; c = nc;
            }
            f[65] = dy;
        }

        float acc[NH] = {};
#pragma unroll
        for (int r = 0; r < NR; r++) {
            float4 p0 = Pt4[r * 2];
            float4 p1 = Pt4[r * 2 + 1];
            float fr = f[r];
            acc[0] += fr * p0.x; acc[1] += fr * p0.y;
            acc[2] += fr * p0.z; acc[3] += fr * p0.w;
            acc[4] += fr * p1.x; acc[5] += fr * p1.y;
            acc[6] += fr * p1.z; acc[7] += fr * p1.w;
        }
#pragma unroll
        for (int h = 0; h < NH; h++)
            s_s[h][j] = g_sc[((size_t)h * NN + i) * NN + j] + acc[h] * SCALE_F;
    }
    __syncthreads();

    // softmax: warp w owns head w
    const int w = tid >> 5, lane = tid & 31;
    float m = -CUDART_INF_F;
    for (int j = lane; j < NN; j += 32) m = fmaxf(m, s_s[w][j]);
#pragma unroll
    for (int o = 16; o; o >>= 1) m = fmaxf(m, __shfl_xor_sync(0xffffffffu, m, o));
    float sum = 0.f;
    for (int j = lane; j < NN; j += 32) {
        float e = __expf(s_s[w][j] - m);
        s_s[w][j] = e;
        sum += e;
    }
#pragma unroll
    for (int o = 16; o; o >>= 1) sum += __shfl_xor_sync(0xffffffffu, sum, o);
    const float inv = __fdividef(1.0f, sum);
    for (int j = lane; j < NN; j += 32)
        g_sc[((size_t)w * NN + i) * NN + j] = s_s[w][j] * inv;
}

// ---------------- K5: O[i, h*64+d] = sum_j attn[h,i,j] * v[j, h*64+d] --
// grid (16 itile, 8 h), block 256, BM=32, BN=64, BK=32
__global__ void av_kernel() {
    const int h = blockIdx.y;
    const int i0 = blockIdx.x * 32;
    __shared__ float At[32][33];
    __shared__ float Vt[32][65];
    const int tid = threadIdx.x, tx = tid & 15, ty = tid >> 4;
    float acc[2][4] = {};
    for (int k0 = 0; k0 < NN; k0 += 32) {
#pragma unroll
        for (int t = 0; t < 4; t++) {
            int idx = tid + t * 256;
            int row = idx >> 5, kk = idx & 31;
            At[row][kk] = g_sc[((size_t)h * NN + i0 + row) * NN + k0 + kk];
        }
#pragma unroll
        for (int t = 0; t < 8; t++) {
            int idx = tid + t * 256;
            int row = idx >> 6, d = idx & 63;
            Vt[row][d] = g_v[(size_t)(k0 + row) * INNER + h * DH + d];
        }
        __syncthreads();
#pragma unroll 8
        for (int kk = 0; kk < 32; kk++) {
            float a0 = At[ty * 2][kk], a1 = At[ty * 2 + 1][kk];
            float b[4];
#pragma unroll
            for (int n = 0; n < 4; n++) b[n] = Vt[kk][tx * 4 + n];
#pragma unroll
            for (int n = 0; n < 4; n++) {
                acc[0][n] += a0 * b[n];
                acc[1][n] += a1 * b[n];
            }
        }
        __syncthreads();
    }
#pragma unroll
    for (int m = 0; m < 2; m++) {
        float4 r = make_float4(acc[m][0], acc[m][1], acc[m][2], acc[m][3]);
        *reinterpret_cast<float4*>(&g_ao[(size_t)(i0 + ty * 2 + m) * INNER + h * DH + tx * 4]) = r;
    }
}

// ---------------- K6: out = g_ao @ Wo + bo -----------------------------
// grid (4 ntile, 16 itile), block 256, BM=32, BN=64, BK=32
__global__ void out_kernel(const float* __restrict__ Wo,
                           const float* __restrict__ bo,
                           float* __restrict__ out) {
    const int n0 = blockIdx.x * 64;
    const int i0 = blockIdx.y * 32;
    __shared__ float At[32][33];
    __shared__ float Bt[32][65];
    const int tid = threadIdx.x, tx = tid & 15, ty = tid >> 4;
    float acc[2][4] = {};
    for (int k0 = 0; k0 < INNER; k0 += 32) {
#pragma unroll
        for (int t = 0; t < 4; t++) {
            int idx = tid + t * 256;
            int row = idx >> 5, kk = idx & 31;
            At[row][kk] = g_ao[(size_t)(i0 + row) * INNER + k0 + kk];
        }
#pragma unroll
        for (int t = 0; t < 8; t++) {
            int idx = tid + t * 256;
            int kk = idx >> 6, n = idx & 63;
            Bt[kk][n] = Wo[(size_t)(k0 + kk) * DIMX + n0 + n];
        }
        __syncthreads();
#pragma unroll 8
        for (int kk = 0; kk < 32; kk++) {
            float a0 = At[ty * 2][kk], a1 = At[ty * 2 + 1][kk];
            float b[4];
#pragma unroll
            for (int n = 0; n < 4; n++) b[n] = Bt[kk][tx * 4 + n];
#pragma unroll
            for (int n = 0; n < 4; n++) {
                acc[0][n] += a0 * b[n];
                acc[1][n] += a1 * b[n];
            }
        }
        __syncthreads();
    }
#pragma unroll
    for (int m = 0; m < 2; m++) {
        float b0 = bo[n0 + tx * 4 + 0], b1 = bo[n0 + tx * 4 + 1];
        float b2 = bo[n0 + tx * 4 + 2], b3 = bo[n0 + tx * 4 + 3];
        float4 r = make_float4(acc[m][0] + b0, acc[m][1] + b1,
                               acc[m][2] + b2, acc[m][3] + b3);
        *reinterpret_cast<float4*>(&out[(size_t)(i0 + ty * 2 + m) * DIMX + n0 + tx * 4]) = r;
    }
}

// ---------------- launch ----------------------------------------------
extern "C" void kernel_launch(void* const* d_in, const int* in_sizes, int n_in,
                              void* d_out, int out_size) {
    const float* x   = (const float*)d_in[0];  // (1,512,256)
    const float* pos = (const float*)d_in[1];  // (1,512,2)
    const float* Wq  = (const float*)d_in[2];  // (256,512)
    const float* Wk  = (const float*)d_in[3];  // (322,512)
    const float* Wv  = (const float*)d_in[4];  // (256,512)
    const float* Wo  = (const float*)d_in[5];  // (512,256)
    const float* bo  = (const float*)d_in[6];  // (256,)
    float* out = (float*)d_out;                // (1,512,256)

    qkv_kernel<<<dim3(8, 8, 3), 256>>>(x, Wq, Wk, Wv);
    p_kernel<<<512, 256>>>(Wk);
    cs_kernel<<<dim3(8, 8, 8), 256>>>();
    rpe_softmax_kernel<<<512, 256>>>(pos);
    av_kernel<<<dim3(16, 8), 256>>>();
    out_kernel<<<dim3(4, 16), 256>>>(Wo, bo, out);
}

// round 2
// speedup vs baseline: 1.2557x; 1.2557x over previous
#include <cuda_runtime.h>
#include <math_constants.h>

#define NN 512
#define DIMX 256
#define NH 8
#define DH 64
#define INNER 512
#define NR 66
#define PI_F 3.14159265358979f
#define SCALE_F 0.125f          // 64^-0.5
#define INV_NORM (1.0f/51.0f)
#define DSTEP_F (7.0f*PI_F/15.0f)

// ---------------- scratch (static device allocations) ----------------
__device__ float g_q [NN*INNER];
__device__ float g_kc[NN*INNER];
__device__ float g_v [NN*INNER];
__device__ float g_P [NN*NR*NH];          // [i][r][h]
__device__ float g_sc[(size_t)NN*NH*NN];  // scores/attn, layout [i][h][j]
__device__ float g_ao[NN*INNER];

// ---------------- K1: fused QKV projections (x @ W) -------------------
__global__ void __launch_bounds__(256) qkv_kernel(const float* __restrict__ x,
                           const float* __restrict__ Wq,
                           const float* __restrict__ Wk,
                           const float* __restrict__ Wv) {
    __shared__ float As[16][64];
    __shared__ float Bs[16][64];
    const float* W = (blockIdx.z == 0) ? Wq : ((blockIdx.z == 1) ? Wk : Wv);
    float* out = (blockIdx.z == 0) ? g_q : ((blockIdx.z == 1) ? g_kc : g_v);
    const int n0 = blockIdx.x * 64, m0 = blockIdx.y * 64;
    const int tid = threadIdx.x;
    const int tx = tid & 15, ty = tid >> 4;

    float acc[4][4] = {};
    for (int k0 = 0; k0 < DIMX; k0 += 16) {
#pragma unroll
        for (int t = 0; t < 4; t++) {
            int idx = tid + t * 256;
            int m = idx >> 4, k = idx & 15;
            As[k][m] = x[(m0 + m) * DIMX + k0 + k];
        }
#pragma unroll
        for (int t = 0; t < 4; t++) {
            int idx = tid + t * 256;
            int k = idx >> 6, n = idx & 63;
            Bs[k][n] = W[(k0 + k) * INNER + n0 + n];
        }
        __syncthreads();
#pragma unroll
        for (int kk = 0; kk < 16; kk++) {
            float4 a = *reinterpret_cast<const float4*>(&As[kk][ty * 4]);
            float4 b = *reinterpret_cast<const float4*>(&Bs[kk][tx * 4]);
            float av[4] = {a.x, a.y, a.z, a.w};
            float bv[4] = {b.x, b.y, b.z, b.w};
#pragma unroll
            for (int i = 0; i < 4; i++)
#pragma unroll
                for (int j = 0; j < 4; j++) acc[i][j] += av[i] * bv[j];
        }
        __syncthreads();
    }
#pragma unroll
    for (int i = 0; i < 4; i++) {
        float4 r = make_float4(acc[i][0], acc[i][1], acc[i][2], acc[i][3]);
        *reinterpret_cast<float4*>(&out[(m0 + ty * 4 + i) * INNER + n0 + tx * 4]) = r;
    }
}

// ---------------- K2: P[i][r][h] = sum_d q[i,h*64+d] * Wk_r[r, h*64+d] --
__global__ void __launch_bounds__(256) p_kernel(const float* __restrict__ Wk) {
    const float* Wr = Wk + (size_t)DIMX * INNER;
    const int i = blockIdx.x;
    __shared__ float qs[INNER];
    const int tid = threadIdx.x;
    qs[tid]       = g_q[i * INNER + tid];
    qs[tid + 256] = g_q[i * INNER + tid + 256];
    __syncthreads();
    for (int t = tid; t < NH * NR; t += 256) {
        int h = t / NR, r = t % NR;
        const float4* w  = reinterpret_cast<const float4*>(Wr + (size_t)r * INNER + h * DH);
        const float4* qq = reinterpret_cast<const float4*>(qs + h * DH);
        float acc = 0.f;
#pragma unroll
        for (int u = 0; u < 16; u++) {
            float4 wv = w[u];
            float4 qv = qq[u];
            acc += wv.x * qv.x + wv.y * qv.y + wv.z * qv.z + wv.w * qv.w;
        }
        g_P[((size_t)i * NR + r) * NH + h] = acc;
    }
}

// ---------------- K3: content scores  S[i,h,j] = scale * q_h[i] . kc_h[j] --
__global__ void __launch_bounds__(256) cs_kernel() {
    const int h = blockIdx.z;
    const int j0 = blockIdx.x * 64, i0 = blockIdx.y * 64;
    __shared__ float Qs[64][65];
    __shared__ float Ks[64][65];
    const int tid = threadIdx.x, tx = tid & 15, ty = tid >> 4;
#pragma unroll
    for (int t = 0; t < 16; t++) {
        int idx = tid + t * 256;
        int row = idx >> 6, d = idx & 63;
        Qs[row][d] = g_q [(i0 + row) * INNER + h * DH + d];
        Ks[row][d] = g_kc[(j0 + row) * INNER + h * DH + d];
    }
    __syncthreads();
    float acc[4][4] = {};
#pragma unroll 8
    for (int d = 0; d < 64; d++) {
        float a[4], b[4];
#pragma unroll
        for (int m = 0; m < 4; m++) a[m] = Qs[ty * 4 + m][d];
#pragma unroll
        for (int n = 0; n < 4; n++) b[n] = Ks[tx * 4 + n][d];
#pragma unroll
        for (int m = 0; m < 4; m++)
#pragma unroll
            for (int n = 0; n < 4; n++) acc[m][n] += a[m] * b[n];
    }
#pragma unroll
    for (int m = 0; m < 4; m++) {
        int i = i0 + ty * 4 + m;
        float4 r = make_float4(acc[m][0] * SCALE_F, acc[m][1] * SCALE_F,
                               acc[m][2] * SCALE_F, acc[m][3] * SCALE_F);
        *reinterpret_cast<float4*>(&g_sc[((size_t)i * NH + h) * NN + j0 + tx * 4]) = r;
    }
}

// ---------------- K4: RPE features + score add + softmax --------------
// grid (512), block 256; each thread handles j = tid and j = tid+256 together
__global__ void __launch_bounds__(256, 3) rpe_softmax_kernel(const float* __restrict__ pos) {
    const int i = blockIdx.x;
    __shared__ float Ps[NR * NH];     // [r][h]
    __shared__ float s_s[NH][NN];
    const int tid = threadIdx.x;
    for (int t = tid; t < NR * NH; t += 256) Ps[t] = g_P[(size_t)i * NR * NH + t];
    __syncthreads();

    const float2* pos2 = reinterpret_cast<const float2*>(pos);
    const float2 pq = pos2[i];
    const float4* Pt4 = reinterpret_cast<const float4*>(Ps);

    const int ja = tid, jb = tid + 256;
    const float2 pka = pos2[ja];
    const float2 pkb = pos2[jb];
    float dxa = (pka.x - pq.x) * INV_NORM; dxa = __fdividef(dxa, 1.f + fabsf(dxa));
    float dya = (pka.y - pq.y) * INV_NORM; dya = __fdividef(dya, 1.f + fabsf(dya));
    float dxb = (pkb.x - pq.x) * INV_NORM; dxb = __fdividef(dxb, 1.f + fabsf(dxb));
    float dyb = (pkb.y - pq.y) * INV_NORM; dyb = __fdividef(dyb, 1.f + fabsf(dyb));

    float A0[8] = {};  // acc for ja
    float A1[8] = {};  // acc for jb

    // ---- x axis: rows k (sin), 16+k (cos), 32 (identity) ----
    {
        float sa, ca, sb, cb, sda, cda, sdb, cdb;
        __sincosf(dxa * PI_F, &sa, &ca);  __sincosf(dxa * DSTEP_F, &sda, &cda);
        __sincosf(dxb * PI_F, &sb, &cb);  __sincosf(dxb * DSTEP_F, &sdb, &cdb);
#pragma unroll
        for (int k = 0; k < 16; k++) {
            float4 p0 = Pt4[2 * k],          p1 = Pt4[2 * k + 1];
            float4 q0 = Pt4[2 * (16 + k)],   q1 = Pt4[2 * (16 + k) + 1];
            A0[0] += sa * p0.x + ca * q0.x;  A1[0] += sb * p0.x + cb * q0.x;
            A0[1] += sa * p0.y + ca * q0.y;  A1[1] += sb * p0.y + cb * q0.y;
            A0[2] += sa * p0.z + ca * q0.z;  A1[2] += sb * p0.z + cb * q0.z;
            A0[3] += sa * p0.w + ca * q0.w;  A1[3] += sb * p0.w + cb * q0.w;
            A0[4] += sa * p1.x + ca * q1.x;  A1[4] += sb * p1.x + cb * q1.x;
            A0[5] += sa * p1.y + ca * q1.y;  A1[5] += sb * p1.y + cb * q1.y;
            A0[6] += sa * p1.z + ca * q1.z;  A1[6] += sb * p1.z + cb * q1.z;
            A0[7] += sa * p1.w + ca * q1.w;  A1[7] += sb * p1.w + cb * q1.w;
            float ns = sa * cda + ca * sda, nc = ca * cda - sa * sda; sa = ns; ca = nc;
            ns = sb * cdb + cb * sdb; nc = cb * cdb - sb * sdb; sb = ns; cb = nc;
        }
        float4 p0 = Pt4[64], p1 = Pt4[65];
        A0[0] += dxa * p0.x; A0[1] += dxa * p0.y; A0[2] += dxa * p0.z; A0[3] += dxa * p0.w;
        A0[4] += dxa * p1.x; A0[5] += dxa * p1.y; A0[6] += dxa * p1.z; A0[7] += dxa * p1.w;
        A1[0] += dxb * p0.x; A1[1] += dxb * p0.y; A1[2] += dxb * p0.z; A1[3] += dxb * p0.w;
        A1[4] += dxb * p1.x; A1[5] += dxb * p1.y; A1[6] += dxb * p1.z; A1[7] += dxb * p1.w;
    }
    // ---- y axis: rows 33+k (sin), 49+k (cos), 65 (identity) ----
    {
        float sa, ca, sb, cb, sda, cda, sdb, cdb;
        __sincosf(dya * PI_F, &sa, &ca);  __sincosf(dya * DSTEP_F, &sda, &cda);
        __sincosf(dyb * PI_F, &sb, &cb);  __sincosf(dyb * DSTEP_F, &sdb, &cdb);
#pragma unroll
        for (int k = 0; k < 16; k++) {
            float4 p0 = Pt4[2 * (33 + k)],   p1 = Pt4[2 * (33 + k) + 1];
            float4 q0 = Pt4[2 * (49 + k)],   q1 = Pt4[2 * (49 + k) + 1];
            A0[0] += sa * p0.x + ca * q0.x;  A1[0] += sb * p0.x + cb * q0.x;
            A0[1] += sa * p0.y + ca * q0.y;  A1[1] += sb * p0.y + cb * q0.y;
            A0[2] += sa * p0.z + ca * q0.z;  A1[2] += sb * p0.z + cb * q0.z;
            A0[3] += sa * p0.w + ca * q0.w;  A1[3] += sb * p0.w + cb * q0.w;
            A0[4] += sa * p1.x + ca * q1.x;  A1[4] += sb * p1.x + cb * q1.x;
            A0[5] += sa * p1.y + ca * q1.y;  A1[5] += sb * p1.y + cb * q1.y;
            A0[6] += sa * p1.z + ca * q1.z;  A1[6] += sb * p1.z + cb * q1.z;
            A0[7] += sa * p1.w + ca * q1.w;  A1[7] += sb * p1.w + cb * q1.w;
            float ns = sa * cda + ca * sda, nc = ca * cda - sa * sda; sa = ns; ca = nc;
            ns = sb * cdb + cb * sdb; nc = cb * cdb - sb * sdb; sb = ns; cb = nc;
        }
        float4 p0 = Pt4[130], p1 = Pt4[131];
        A0[0] += dya * p0.x; A0[1] += dya * p0.y; A0[2] += dya * p0.z; A0[3] += dya * p0.w;
        A0[4] += dya * p1.x; A0[5] += dya * p1.y; A0[6] += dya * p1.z; A0[7] += dya * p1.w;
        A1[0] += dyb * p0.x; A1[1] += dyb * p0.y; A1[2] += dyb * p0.z; A1[3] += dyb * p0.w;
        A1[4] += dyb * p1.x; A1[5] += dyb * p1.y; A1[6] += dyb * p1.z; A1[7] += dyb * p1.w;
    }

    const float* csrow = g_sc + (size_t)i * NH * NN;
#pragma unroll
    for (int h = 0; h < NH; h++) {
        s_s[h][ja] = csrow[h * NN + ja] + A0[h] * SCALE_F;
        s_s[h][jb] = csrow[h * NN + jb] + A1[h] * SCALE_F;
    }
    __syncthreads();

    // softmax: warp w owns head w
    const int w = tid >> 5, lane = tid & 31;
    float m = -CUDART_INF_F;
    for (int j = lane; j < NN; j += 32) m = fmaxf(m, s_s[w][j]);
#pragma unroll
    for (int o = 16; o; o >>= 1) m = fmaxf(m, __shfl_xor_sync(0xffffffffu, m, o));
    float sum = 0.f;
    for (int j = lane; j < NN; j += 32) {
        float e = __expf(s_s[w][j] - m);
        s_s[w][j] = e;
        sum += e;
    }
#pragma unroll
    for (int o = 16; o; o >>= 1) sum += __shfl_xor_sync(0xffffffffu, sum, o);
    const float inv = __fdividef(1.0f, sum);
    float* arow = g_sc + (size_t)i * NH * NN + (size_t)w * NN;
    for (int j = lane; j < NN; j += 32)
        arow[j] = s_s[w][j] * inv;
}

// ---------------- K5: O[i, h*64+d] = sum_j attn[i,h,j] * v[j, h*64+d] --
__global__ void __launch_bounds__(256) av_kernel() {
    const int h = blockIdx.y;
    const int i0 = blockIdx.x * 32;
    __shared__ float At[32][33];
    __shared__ float Vt[32][65];
    const int tid = threadIdx.x, tx = tid & 15, ty = tid >> 4;
    float acc[2][4] = {};
    for (int k0 = 0; k0 < NN; k0 += 32) {
#pragma unroll
        for (int t = 0; t < 4; t++) {
            int idx = tid + t * 256;
            int row = idx >> 5, kk = idx & 31;
            At[row][kk] = g_sc[((size_t)(i0 + row) * NH + h) * NN + k0 + kk];
        }
#pragma unroll
        for (int t = 0; t < 8; t++) {
            int idx = tid + t * 256;
            int row = idx >> 6, d = idx & 63;
            Vt[row][d] = g_v[(size_t)(k0 + row) * INNER + h * DH + d];
        }
        __syncthreads();
#pragma unroll 8
        for (int kk = 0; kk < 32; kk++) {
            float a0 = At[ty * 2][kk], a1 = At[ty * 2 + 1][kk];
            float b[4];
#pragma unroll
            for (int n = 0; n < 4; n++) b[n] = Vt[kk][tx * 4 + n];
#pragma unroll
            for (int n = 0; n < 4; n++) {
                acc[0][n] += a0 * b[n];
                acc[1][n] += a1 * b[n];
            }
        }
        __syncthreads();
    }
#pragma unroll
    for (int m = 0; m < 2; m++) {
        float4 r = make_float4(acc[m][0], acc[m][1], acc[m][2], acc[m][3]);
        *reinterpret_cast<float4*>(&g_ao[(size_t)(i0 + ty * 2 + m) * INNER + h * DH + tx * 4]) = r;
    }
}

// ---------------- K6: out = g_ao @ Wo + bo -----------------------------
__global__ void __launch_bounds__(256) out_kernel(const float* __restrict__ Wo,
                           const float* __restrict__ bo,
                           float* __restrict__ out) {
    const int n0 = blockIdx.x * 64;
    const int i0 = blockIdx.y * 32;
    __shared__ float At[32][33];
    __shared__ float Bt[32][65];
    const int tid = threadIdx.x, tx = tid & 15, ty = tid >> 4;
    float acc[2][4] = {};
    for (int k0 = 0; k0 < INNER; k0 += 32) {
#pragma unroll
        for (int t = 0; t < 4; t++) {
            int idx = tid + t * 256;
            int row = idx >> 5, kk = idx & 31;
            At[row][kk] = g_ao[(size_t)(i0 + row) * INNER + k0 + kk];
        }
#pragma unroll
        for (int t = 0; t < 8; t++) {
            int idx = tid + t * 256;
            int kk = idx >> 6, n = idx & 63;
            Bt[kk][n] = Wo[(size_t)(k0 + kk) * DIMX + n0 + n];
        }
        __syncthreads();
#pragma unroll 8
        for (int kk = 0; kk < 32; kk++) {
            float a0 = At[ty * 2][kk], a1 = At[ty * 2 + 1][kk];
            float b[4];
#pragma unroll
            for (int n = 0; n < 4; n++) b[n] = Bt[kk][tx * 4 + n];
#pragma unroll
            for (int n = 0; n < 4; n++) {
                acc[0][n] += a0 * b[n];
                acc[1][n] += a1 * b[n];
            }
        }
        __syncthreads();
    }
#pragma unroll
    for (int m = 0; m < 2; m++) {
        float b0 = bo[n0 + tx * 4 + 0], b1 = bo[n0 + tx * 4 + 1];
        float b2 = bo[n0 + tx * 4 + 2], b3 = bo[n0 + tx * 4 + 3];
        float4 r = make_float4(acc[m][0] + b0, acc[m][1] + b1,
                               acc[m][2] + b2, acc[m][3] + b3);
        *reinterpret_cast<float4*>(&out[(size_t)(i0 + ty * 2 + m) * DIMX + n0 + tx * 4]) = r;
    }
}

// ---------------- launch ----------------------------------------------
extern "C" void kernel_launch(void* const* d_in, const int* in_sizes, int n_in,
                              void* d_out, int out_size) {
    const float* x   = (const float*)d_in[0];
    const float* pos = (const float*)d_in[1];
    const float* Wq  = (const float*)d_in[2];
    const float* Wk  = (const float*)d_in[3];
    const float* Wv  = (const float*)d_in[4];
    const float* Wo  = (const float*)d_in[5];
    const float* bo  = (const float*)d_in[6];
    float* out = (float*)d_out;

    qkv_kernel<<<dim3(8, 8, 3), 256>>>(x, Wq, Wk, Wv);
    p_kernel<<<512, 256>>>(Wk);
    cs_kernel<<<dim3(8, 8, 8), 256>>>();
    rpe_softmax_kernel<<<512, 256>>>(pos);
    av_kernel<<<dim3(16, 8), 256>>>();
    out_kernel<<<dim3(4, 16), 256>>>(Wo, bo, out);
}

// round 3
// speedup vs baseline: 1.6942x; 1.3492x over previous
#include <cuda_runtime.h>
#include <math_constants.h>

#define NN 512
#define DIMX 256
#define NH 8
#define DH 64
#define INNER 512
#define NR 66
#define PI_F 3.14159265358979f
#define SCALE_F 0.125f
#define INV_NORM (1.0f/51.0f)
#define DSTEP_F (7.0f*PI_F/15.0f)

// ---------------- scratch ----------------
__device__ float g_q [NN*INNER];
__device__ float g_kc[NN*INNER];
__device__ float g_v [NN*INNER];
__device__ float g_P [NN*NR*NH];          // [i][r][h]
__device__ float g_sc[(size_t)NN*NH*NN];  // scores/attn, [i][h][j]
__device__ float g_ao[NN*INNER];

// ---------------- K1: QKV projections, 64x64 tiles, K-chunk 32, reg prefetch --
__global__ void __launch_bounds__(256) qkv_kernel(const float* __restrict__ x,
                           const float* __restrict__ Wq,
                           const float* __restrict__ Wk,
                           const float* __restrict__ Wv) {
    __shared__ float As[32][68];
    __shared__ float Bs[32][68];
    const float* W = (blockIdx.z == 0) ? Wq : ((blockIdx.z == 1) ? Wk : Wv);
    float* out = (blockIdx.z == 0) ? g_q : ((blockIdx.z == 1) ? g_kc : g_v);
    const int n0 = blockIdx.x * 64, m0 = blockIdx.y * 64;
    const int tid = threadIdx.x, tx = tid & 15, ty = tid >> 4;
    const int am = tid >> 2, ac = tid & 3;
    const int bk = tid >> 3, bc = tid & 7;
    const float* xrow  = x + (size_t)(m0 + am) * DIMX;
    const float* wbase = W + n0;

    float4 ra0 = *(const float4*)&xrow[ac * 4];
    float4 ra1 = *(const float4*)&xrow[ac * 4 + 16];
    float4 rb0 = *(const float4*)&wbase[(size_t)bk * INNER + bc * 4];
    float4 rb1 = *(const float4*)&wbase[(size_t)bk * INNER + bc * 4 + 32];

    float acc[4][4] = {};
    for (int c = 0; c < 8; c++) {
        As[ac*4+0][am] = ra0.x; As[ac*4+1][am] = ra0.y;
        As[ac*4+2][am] = ra0.z; As[ac*4+3][am] = ra0.w;
        As[ac*4+16][am] = ra1.x; As[ac*4+17][am] = ra1.y;
        As[ac*4+18][am] = ra1.z; As[ac*4+19][am] = ra1.w;
        *(float4*)&Bs[bk][bc*4]      = rb0;
        *(float4*)&Bs[bk][bc*4 + 32] = rb1;
        __syncthreads();
        if (c < 7) {
            int k0 = (c + 1) * 32;
            ra0 = *(const float4*)&xrow[k0 + ac * 4];
            ra1 = *(const float4*)&xrow[k0 + ac * 4 + 16];
            rb0 = *(const float4*)&wbase[(size_t)(k0 + bk) * INNER + bc * 4];
            rb1 = *(const float4*)&wbase[(size_t)(k0 + bk) * INNER + bc * 4 + 32];
        }
#pragma unroll
        for (int kk = 0; kk < 32; kk++) {
            float4 a = *(const float4*)&As[kk][ty * 4];
            float4 b = *(const float4*)&Bs[kk][tx * 4];
            float av[4] = {a.x, a.y, a.z, a.w};
            float bv[4] = {b.x, b.y, b.z, b.w};
#pragma unroll
            for (int i = 0; i < 4; i++)
#pragma unroll
                for (int j = 0; j < 4; j++) acc[i][j] += av[i] * bv[j];
        }
        __syncthreads();
    }
#pragma unroll
    for (int i = 0; i < 4; i++) {
        float4 r = make_float4(acc[i][0], acc[i][1], acc[i][2], acc[i][3]);
        *(float4*)&out[(size_t)(m0 + ty * 4 + i) * INNER + n0 + tx * 4] = r;
    }
}

// ---------------- K2: combined content scores (z<8) + P (z==8) --------
__global__ void __launch_bounds__(256) cs_p_kernel(const float* __restrict__ Wk) {
    __shared__ float sm[2 * 64 * 68];
    const int tid = threadIdx.x;
    if (blockIdx.z < 8) {
        float (*Qs)[68] = (float(*)[68])sm;
        float (*Ks)[68] = (float(*)[68])(sm + 64 * 68);
        const int h = blockIdx.z;
        const int j0 = blockIdx.x * 64, i0 = blockIdx.y * 64;
        const int row = tid >> 2, c = tid & 3;
        const float* qrow = g_q  + (size_t)(i0 + row) * INNER + h * DH;
        const float* krow = g_kc + (size_t)(j0 + row) * INNER + h * DH;
#pragma unroll
        for (int u = 0; u < 4; u++) {
            int d = (c + 4 * u) * 4;
            float4 qv = *(const float4*)&qrow[d];
            float4 kv = *(const float4*)&krow[d];
            Qs[d][row] = qv.x; Qs[d+1][row] = qv.y; Qs[d+2][row] = qv.z; Qs[d+3][row] = qv.w;
            Ks[d][row] = kv.x; Ks[d+1][row] = kv.y; Ks[d+2][row] = kv.z; Ks[d+3][row] = kv.w;
        }
        __syncthreads();
        const int tx = tid & 15, ty = tid >> 4;
        float acc[4][4] = {};
#pragma unroll
        for (int kk = 0; kk < 64; kk++) {
            float4 a = *(const float4*)&Qs[kk][ty * 4];
            float4 b = *(const float4*)&Ks[kk][tx * 4];
            float av[4] = {a.x, a.y, a.z, a.w};
            float bv[4] = {b.x, b.y, b.z, b.w};
#pragma unroll
            for (int m = 0; m < 4; m++)
#pragma unroll
                for (int n = 0; n < 4; n++) acc[m][n] += av[m] * bv[n];
        }
#pragma unroll
        for (int m = 0; m < 4; m++) {
            int i = i0 + ty * 4 + m;
            float4 r = make_float4(acc[m][0]*SCALE_F, acc[m][1]*SCALE_F,
                                   acc[m][2]*SCALE_F, acc[m][3]*SCALE_F);
            *(float4*)&g_sc[((size_t)i * NH + h) * NN + j0 + tx * 4] = r;
        }
    } else {
        // P[i][r][h] for 8 queries
        float* qs = sm;   // [8][512]
        const int i0 = (blockIdx.y * 8 + blockIdx.x) * 8;
        const float4* src = (const float4*)(g_q + (size_t)i0 * INNER);
#pragma unroll
        for (int u = 0; u < 4; u++) ((float4*)qs)[tid + u * 256] = src[tid + u * 256];
        __syncthreads();
        for (int tt = tid; tt < 528; tt += 256) {
            int r = tt >> 3, h = tt & 7;
            const float4* w4 = (const float4*)(Wk + (size_t)(DIMX + r) * INNER + h * DH);
            float acc[8] = {};
#pragma unroll
            for (int u = 0; u < 16; u++) {
                float4 wv = w4[u];
#pragma unroll
                for (int i = 0; i < 8; i++) {
                    float4 qv = *(const float4*)&qs[i * INNER + h * DH + u * 4];
                    acc[i] += wv.x*qv.x + wv.y*qv.y + wv.z*qv.z + wv.w*qv.w;
                }
            }
#pragma unroll
            for (int i = 0; i < 8; i++)
                g_P[((size_t)(i0 + i) * NR + r) * NH + h] = acc[i];
        }
    }
}

// ---------------- K3: RPE features + score add + softmax --------------
__global__ void __launch_bounds__(256, 3) rpe_softmax_kernel(const float* __restrict__ pos) {
    const int i = blockIdx.x;
    __shared__ float Ps[NR * NH];
    __shared__ float s_s[NH][NN];
    const int tid = threadIdx.x;
    for (int t = tid; t < NR * NH; t += 256) Ps[t] = g_P[(size_t)i * NR * NH + t];
    __syncthreads();

    const float2* pos2 = reinterpret_cast<const float2*>(pos);
    const float2 pq = pos2[i];
    const float4* Pt4 = reinterpret_cast<const float4*>(Ps);

    const int ja = tid, jb = tid + 256;
    const float2 pka = pos2[ja];
    const float2 pkb = pos2[jb];
    float dxa = (pka.x - pq.x) * INV_NORM; dxa = __fdividef(dxa, 1.f + fabsf(dxa));
    float dya = (pka.y - pq.y) * INV_NORM; dya = __fdividef(dya, 1.f + fabsf(dya));
    float dxb = (pkb.x - pq.x) * INV_NORM; dxb = __fdividef(dxb, 1.f + fabsf(dxb));
    float dyb = (pkb.y - pq.y) * INV_NORM; dyb = __fdividef(dyb, 1.f + fabsf(dyb));

    float A0[8] = {};
    float A1[8] = {};
    {
        float sa, ca, sb, cb, sda, cda, sdb, cdb;
        __sincosf(dxa * PI_F, &sa, &ca);  __sincosf(dxa * DSTEP_F, &sda, &cda);
        __sincosf(dxb * PI_F, &sb, &cb);  __sincosf(dxb * DSTEP_F, &sdb, &cdb);
#pragma unroll
        for (int k = 0; k < 16; k++) {
            float4 p0 = Pt4[2 * k],        p1 = Pt4[2 * k + 1];
            float4 q0 = Pt4[2 * (16 + k)], q1 = Pt4[2 * (16 + k) + 1];
            A0[0] += sa*p0.x + ca*q0.x;  A1[0] += sb*p0.x + cb*q0.x;
            A0[1] += sa*p0.y + ca*q0.y;  A1[1] += sb*p0.y + cb*q0.y;
            A0[2] += sa*p0.z + ca*q0.z;  A1[2] += sb*p0.z + cb*q0.z;
            A0[3] += sa*p0.w + ca*q0.w;  A1[3] += sb*p0.w + cb*q0.w;
            A0[4] += sa*p1.x + ca*q1.x;  A1[4] += sb*p1.x + cb*q1.x;
            A0[5] += sa*p1.y + ca*q1.y;  A1[5] += sb*p1.y + cb*q1.y;
            A0[6] += sa*p1.z + ca*q1.z;  A1[6] += sb*p1.z + cb*q1.z;
            A0[7] += sa*p1.w + ca*q1.w;  A1[7] += sb*p1.w + cb*q1.w;
            float ns = sa*cda + ca*sda, nc = ca*cda - sa*sda; sa = ns; ca = nc;
            ns = sb*cdb + cb*sdb; nc = cb*cdb - sb*sdb; sb = ns; cb = nc;
        }
        float4 p0 = Pt4[64], p1 = Pt4[65];
        A0[0] += dxa*p0.x; A0[1] += dxa*p0.y; A0[2] += dxa*p0.z; A0[3] += dxa*p0.w;
        A0[4] += dxa*p1.x; A0[5] += dxa*p1.y; A0[6] += dxa*p1.z; A0[7] += dxa*p1.w;
        A1[0] += dxb*p0.x; A1[1] += dxb*p0.y; A1[2] += dxb*p0.z; A1[3] += dxb*p0.w;
        A1[4] += dxb*p1.x; A1[5] += dxb*p1.y; A1[6] += dxb*p1.z; A1[7] += dxb*p1.w;
    }
    {
        float sa, ca, sb, cb, sda, cda, sdb, cdb;
        __sincosf(dya * PI_F, &sa, &ca);  __sincosf(dya * DSTEP_F, &sda, &cda);
        __sincosf(dyb * PI_F, &sb, &cb);  __sincosf(dyb * DSTEP_F, &sdb, &cdb);
#pragma unroll
        for (int k = 0; k < 16; k++) {
            float4 p0 = Pt4[2 * (33 + k)], p1 = Pt4[2 * (33 + k) + 1];
            float4 q0 = Pt4[2 * (49 + k)], q1 = Pt4[2 * (49 + k) + 1];
            A0[0] += sa*p0.x + ca*q0.x;  A1[0] += sb*p0.x + cb*q0.x;
            A0[1] += sa*p0.y + ca*q0.y;  A1[1] += sb*p0.y + cb*q0.y;
            A0[2] += sa*p0.z + ca*q0.z;  A1[2] += sb*p0.z + cb*q0.z;
            A0[3] += sa*p0.w + ca*q0.w;  A1[3] += sb*p0.w + cb*q0.w;
            A0[4] += sa*p1.x + ca*q1.x;  A1[4] += sb*p1.x + cb*q1.x;
            A0[5] += sa*p1.y + ca*q1.y;  A1[5] += sb*p1.y + cb*q1.y;
            A0[6] += sa*p1.z + ca*q1.z;  A1[6] += sb*p1.z + cb*q1.z;
            A0[7] += sa*p1.w + ca*q1.w;  A1[7] += sb*p1.w + cb*q1.w;
            float ns = sa*cda + ca*sda, nc = ca*cda - sa*sda; sa = ns; ca = nc;
            ns = sb*cdb + cb*sdb; nc = cb*cdb - sb*sdb; sb = ns; cb = nc;
        }
        float4 p0 = Pt4[130], p1 = Pt4[131];
        A0[0] += dya*p0.x; A0[1] += dya*p0.y; A0[2] += dya*p0.z; A0[3] += dya*p0.w;
        A0[4] += dya*p1.x; A0[5] += dya*p1.y; A0[6] += dya*p1.z; A0[7] += dya*p1.w;
        A1[0] += dyb*p0.x; A1[1] += dyb*p0.y; A1[2] += dyb*p0.z; A1[3] += dyb*p0.w;
        A1[4] += dyb*p1.x; A1[5] += dyb*p1.y; A1[6] += dyb*p1.z; A1[7] += dyb*p1.w;
    }

    const float* csrow = g_sc + (size_t)i * NH * NN;
#pragma unroll
    for (int h = 0; h < NH; h++) {
        s_s[h][ja] = csrow[h * NN + ja] + A0[h] * SCALE_F;
        s_s[h][jb] = csrow[h * NN + jb] + A1[h] * SCALE_F;
    }
    __syncthreads();

    const int w = tid >> 5, lane = tid & 31;
    float m = -CUDART_INF_F;
    for (int j = lane; j < NN; j += 32) m = fmaxf(m, s_s[w][j]);
#pragma unroll
    for (int o = 16; o; o >>= 1) m = fmaxf(m, __shfl_xor_sync(0xffffffffu, m, o));
    float sum = 0.f;
    for (int j = lane; j < NN; j += 32) {
        float e = __expf(s_s[w][j] - m);
        s_s[w][j] = e;
        sum += e;
    }
#pragma unroll
    for (int o = 16; o; o >>= 1) sum += __shfl_xor_sync(0xffffffffu, sum, o);
    const float inv = __fdividef(1.0f, sum);
    float* arow = g_sc + (size_t)i * NH * NN + (size_t)w * NN;
    for (int j = lane; j < NN; j += 32)
        arow[j] = s_s[w][j] * inv;
}

// ---------------- K4: attn @ V, 32x64 tiles, K-chunk 64, reg prefetch --
__global__ void __launch_bounds__(256) av_kernel() {
    const int h = blockIdx.y;
    const int i0 = blockIdx.x * 32;
    __shared__ float At[64][34];
    __shared__ float Vt[64][68];
    const int tid = threadIdx.x, tx = tid & 15, ty = tid >> 4;
    const int ai = tid >> 3, aj = tid & 7;
    const int vj = tid >> 2, vc = tid & 3;
    const float* arow  = g_sc + ((size_t)(i0 + ai) * NH + h) * NN;
    const float* vbase = g_v + h * DH;

    float4 pa0 = *(const float4*)&arow[aj * 4];
    float4 pa1 = *(const float4*)&arow[aj * 4 + 32];
    float4 pv[4];
#pragma unroll
    for (int u = 0; u < 4; u++)
        pv[u] = *(const float4*)&vbase[(size_t)vj * INNER + (vc + 4 * u) * 4];

    float acc[2][4] = {};
    for (int c = 0; c < 8; c++) {
        At[aj*4+0][ai] = pa0.x; At[aj*4+1][ai] = pa0.y;
        At[aj*4+2][ai] = pa0.z; At[aj*4+3][ai] = pa0.w;
        At[aj*4+32][ai] = pa1.x; At[aj*4+33][ai] = pa1.y;
        At[aj*4+34][ai] = pa1.z; At[aj*4+35][ai] = pa1.w;
#pragma unroll
        for (int u = 0; u < 4; u++)
            *(float4*)&Vt[vj][(vc + 4 * u) * 4] = pv[u];
        __syncthreads();
        if (c < 7) {
            int k0 = (c + 1) * 64;
            pa0 = *(const float4*)&arow[k0 + aj * 4];
            pa1 = *(const float4*)&arow[k0 + aj * 4 + 32];
#pragma unroll
            for (int u = 0; u < 4; u++)
                pv[u] = *(const float4*)&vbase[(size_t)(k0 + vj) * INNER + (vc + 4 * u) * 4];
        }
#pragma unroll
        for (int kk = 0; kk < 64; kk++) {
            float2 a = *(const float2*)&At[kk][ty * 2];
            float4 b = *(const float4*)&Vt[kk][tx * 4];
            acc[0][0] += a.x * b.x; acc[0][1] += a.x * b.y;
            acc[0][2] += a.x * b.z; acc[0][3] += a.x * b.w;
            acc[1][0] += a.y * b.x; acc[1][1] += a.y * b.y;
            acc[1][2] += a.y * b.z; acc[1][3] += a.y * b.w;
        }
        __syncthreads();
    }
#pragma unroll
    for (int m = 0; m < 2; m++) {
        float4 r = make_float4(acc[m][0], acc[m][1], acc[m][2], acc[m][3]);
        *(float4*)&g_ao[(size_t)(i0 + ty * 2 + m) * INNER + h * DH + tx * 4] = r;
    }
}

// ---------------- K5: out = g_ao @ Wo + bo, 16x64 tiles, prefetch ------
__global__ void __launch_bounds__(256) out_kernel(const float* __restrict__ Wo,
                           const float* __restrict__ bo,
                           float* __restrict__ out) {
    const int n0 = blockIdx.x * 64;
    const int i0 = blockIdx.y * 16;
    __shared__ float At[64][17];
    __shared__ float Bt[64][68];
    const int tid = threadIdx.x;
    const int ti = tid >> 4, tn = tid & 15;
    const int ak = tid & 15;                 // A fill: i=ti, f4 at k=ak*4
    const int bkr = tid >> 2, bc2 = tid & 3;
    const float* aor  = g_ao + (size_t)(i0 + ti) * INNER;
    const float* wrow = Wo + n0;

    float4 pa = *(const float4*)&aor[ak * 4];
    float4 pb[4];
#pragma unroll
    for (int u = 0; u < 4; u++)
        pb[u] = *(const float4*)&wrow[(size_t)bkr * DIMX + (bc2 + 4 * u) * 4];

    float acc[4] = {};
    for (int c = 0; c < 8; c++) {
        At[ak*4+0][ti] = pa.x; At[ak*4+1][ti] = pa.y;
        At[ak*4+2][ti] = pa.z; At[ak*4+3][ti] = pa.w;
#pragma unroll
        for (int u = 0; u < 4; u++)
            *(float4*)&Bt[bkr][(bc2 + 4 * u) * 4] = pb[u];
        __syncthreads();
        if (c < 7) {
            int k0 = (c + 1) * 64;
            pa = *(const float4*)&aor[k0 + ak * 4];
#pragma unroll
            for (int u = 0; u < 4; u++)
                pb[u] = *(const float4*)&wrow[(size_t)(k0 + bkr) * DIMX + (bc2 + 4 * u) * 4];
        }
#pragma unroll
        for (int kk = 0; kk < 64; kk++) {
            float a = At[kk][ti];
            float4 b = *(const float4*)&Bt[kk][tn * 4];
            acc[0] += a * b.x; acc[1] += a * b.y;
            acc[2] += a * b.z; acc[3] += a * b.w;
        }
        __syncthreads();
    }
    float4 bv = *(const float4*)&bo[n0 + tn * 4];
    float4 r = make_float4(acc[0] + bv.x, acc[1] + bv.y, acc[2] + bv.z, acc[3] + bv.w);
    *(float4*)&out[(size_t)(i0 + ti) * DIMX + n0 + tn * 4] = r;
}

// ---------------- launch ----------------------------------------------
extern "C" void kernel_launch(void* const* d_in, const int* in_sizes, int n_in,
                              void* d_out, int out_size) {
    const float* x   = (const float*)d_in[0];
    const float* pos = (const float*)d_in[1];
    const float* Wq  = (const float*)d_in[2];
    const float* Wk  = (const float*)d_in[3];
    const float* Wv  = (const float*)d_in[4];
    const float* Wo  = (const float*)d_in[5];
    const float* bo  = (const float*)d_in[6];
    float* out = (float*)d_out;

    qkv_kernel<<<dim3(8, 8, 3), 256>>>(x, Wq, Wk, Wv);
    cs_p_kernel<<<dim3(8, 8, 9), 256>>>(Wk);
    rpe_softmax_kernel<<<512, 256>>>(pos);
    av_kernel<<<dim3(16, 8), 256>>>();
    out_kernel<<<dim3(4, 32), 256>>>(Wo, bo, out);
}

// round 4
// speedup vs baseline: 1.7514x; 1.0338x over previous
#include <cuda_runtime.h>
#include <math_constants.h>

#define NN 512
#define DIMX 256
#define NH 8
#define DH 64
#define INNER 512
#define NR 66
#define PI_F 3.14159265358979f
#define SCALE_F 0.125f
#define INV_NORM (1.0f/51.0f)
#define DSTEP_F (7.0f*PI_F/15.0f)

// ---------------- scratch ----------------
__device__ float g_q [NN*INNER];
__device__ float g_kc[NN*INNER];
__device__ float g_v [NN*INNER];
__device__ float g_P [NN*NR*NH];            // [i][r][h]
__device__ float g_sc[(size_t)NN*NH*NN];    // scores/attn, [i][h][j]
__device__ float g_ao[2*(size_t)NN*INNER];  // split-K partials [s][i][hd]

// ---------------- K1: QKV projections, 64x64 tiles, K-chunk 32, reg prefetch --
__global__ void __launch_bounds__(256) qkv_kernel(const float* __restrict__ x,
                           const float* __restrict__ Wq,
                           const float* __restrict__ Wk,
                           const float* __restrict__ Wv) {
    __shared__ float As[32][68];
    __shared__ float Bs[32][68];
    const float* W = (blockIdx.z == 0) ? Wq : ((blockIdx.z == 1) ? Wk : Wv);
    float* out = (blockIdx.z == 0) ? g_q : ((blockIdx.z == 1) ? g_kc : g_v);
    const int n0 = blockIdx.x * 64, m0 = blockIdx.y * 64;
    const int tid = threadIdx.x, tx = tid & 15, ty = tid >> 4;
    const int am = tid >> 2, ac = tid & 3;
    const int bk = tid >> 3, bc = tid & 7;
    const float* xrow  = x + (size_t)(m0 + am) * DIMX;
    const float* wbase = W + n0;

    float4 ra0 = *(const float4*)&xrow[ac * 4];
    float4 ra1 = *(const float4*)&xrow[ac * 4 + 16];
    float4 rb0 = *(const float4*)&wbase[(size_t)bk * INNER + bc * 4];
    float4 rb1 = *(const float4*)&wbase[(size_t)bk * INNER + bc * 4 + 32];

    float acc[4][4] = {};
    for (int c = 0; c < 8; c++) {
        As[ac*4+0][am] = ra0.x; As[ac*4+1][am] = ra0.y;
        As[ac*4+2][am] = ra0.z; As[ac*4+3][am] = ra0.w;
        As[ac*4+16][am] = ra1.x; As[ac*4+17][am] = ra1.y;
        As[ac*4+18][am] = ra1.z; As[ac*4+19][am] = ra1.w;
        *(float4*)&Bs[bk][bc*4]      = rb0;
        *(float4*)&Bs[bk][bc*4 + 32] = rb1;
        __syncthreads();
        if (c < 7) {
            int k0 = (c + 1) * 32;
            ra0 = *(const float4*)&xrow[k0 + ac * 4];
            ra1 = *(const float4*)&xrow[k0 + ac * 4 + 16];
            rb0 = *(const float4*)&wbase[(size_t)(k0 + bk) * INNER + bc * 4];
            rb1 = *(const float4*)&wbase[(size_t)(k0 + bk) * INNER + bc * 4 + 32];
        }
#pragma unroll
        for (int kk = 0; kk < 32; kk++) {
            float4 a = *(const float4*)&As[kk][ty * 4];
            float4 b = *(const float4*)&Bs[kk][tx * 4];
            float av[4] = {a.x, a.y, a.z, a.w};
            float bv[4] = {b.x, b.y, b.z, b.w};
#pragma unroll
            for (int i = 0; i < 4; i++)
#pragma unroll
                for (int j = 0; j < 4; j++) acc[i][j] += av[i] * bv[j];
        }
        __syncthreads();
    }
#pragma unroll
    for (int i = 0; i < 4; i++) {
        float4 r = make_float4(acc[i][0], acc[i][1], acc[i][2], acc[i][3]);
        *(float4*)&out[(size_t)(m0 + ty * 4 + i) * INNER + n0 + tx * 4] = r;
    }
}

// ---------------- K2: combined content scores (z<8) + P (z==8) --------
__global__ void __launch_bounds__(256) cs_p_kernel(const float* __restrict__ Wk) {
    __shared__ float sm[2 * 64 * 68];
    const int tid = threadIdx.x;
    if (blockIdx.z < 8) {
        float (*Qs)[68] = (float(*)[68])sm;
        float (*Ks)[68] = (float(*)[68])(sm + 64 * 68);
        const int h = blockIdx.z;
        const int j0 = blockIdx.x * 64, i0 = blockIdx.y * 64;
        const int row = tid >> 2, c = tid & 3;
        const float* qrow = g_q  + (size_t)(i0 + row) * INNER + h * DH;
        const float* krow = g_kc + (size_t)(j0 + row) * INNER + h * DH;
#pragma unroll
        for (int u = 0; u < 4; u++) {
            int d = (c + 4 * u) * 4;
            float4 qv = *(const float4*)&qrow[d];
            float4 kv = *(const float4*)&krow[d];
            Qs[d][row] = qv.x; Qs[d+1][row] = qv.y; Qs[d+2][row] = qv.z; Qs[d+3][row] = qv.w;
            Ks[d][row] = kv.x; Ks[d+1][row] = kv.y; Ks[d+2][row] = kv.z; Ks[d+3][row] = kv.w;
        }
        __syncthreads();
        const int tx = tid & 15, ty = tid >> 4;
        float acc[4][4] = {};
#pragma unroll
        for (int kk = 0; kk < 64; kk++) {
            float4 a = *(const float4*)&Qs[kk][ty * 4];
            float4 b = *(const float4*)&Ks[kk][tx * 4];
            float av[4] = {a.x, a.y, a.z, a.w};
            float bv[4] = {b.x, b.y, b.z, b.w};
#pragma unroll
            for (int m = 0; m < 4; m++)
#pragma unroll
                for (int n = 0; n < 4; n++) acc[m][n] += av[m] * bv[n];
        }
#pragma unroll
        for (int m = 0; m < 4; m++) {
            int i = i0 + ty * 4 + m;
            float4 r = make_float4(acc[m][0]*SCALE_F, acc[m][1]*SCALE_F,
                                   acc[m][2]*SCALE_F, acc[m][3]*SCALE_F);
            *(float4*)&g_sc[((size_t)i * NH + h) * NN + j0 + tx * 4] = r;
        }
    } else {
        float* qs = sm;
        const int i0 = (blockIdx.y * 8 + blockIdx.x) * 8;
        const float4* src = (const float4*)(g_q + (size_t)i0 * INNER);
#pragma unroll
        for (int u = 0; u < 4; u++) ((float4*)qs)[tid + u * 256] = src[tid + u * 256];
        __syncthreads();
        for (int tt = tid; tt < 528; tt += 256) {
            int r = tt >> 3, h = tt & 7;
            const float4* w4 = (const float4*)(Wk + (size_t)(DIMX + r) * INNER + h * DH);
            float acc[8] = {};
#pragma unroll
            for (int u = 0; u < 16; u++) {
                float4 wv = w4[u];
#pragma unroll
                for (int i = 0; i < 8; i++) {
                    float4 qv = *(const float4*)&qs[i * INNER + h * DH + u * 4];
                    acc[i] += wv.x*qv.x + wv.y*qv.y + wv.z*qv.z + wv.w*qv.w;
                }
            }
#pragma unroll
            for (int i = 0; i < 8; i++)
                g_P[((size_t)(i0 + i) * NR + r) * NH + h] = acc[i];
        }
    }
}

// ---------------- K3: RPE features + score add + softmax --------------
__global__ void __launch_bounds__(256, 3) rpe_softmax_kernel(const float* __restrict__ pos) {
    const int i = blockIdx.x;
    __shared__ float Ps[NR * NH];
    __shared__ float s_s[NH][NN];
    const int tid = threadIdx.x;
    for (int t = tid; t < NR * NH; t += 256) Ps[t] = g_P[(size_t)i * NR * NH + t];
    __syncthreads();

    const float2* pos2 = reinterpret_cast<const float2*>(pos);
    const float2 pq = pos2[i];
    const float4* Pt4 = reinterpret_cast<const float4*>(Ps);

    const int ja = tid, jb = tid + 256;
    const float2 pka = pos2[ja];
    const float2 pkb = pos2[jb];
    float dxa = (pka.x - pq.x) * INV_NORM; dxa = __fdividef(dxa, 1.f + fabsf(dxa));
    float dya = (pka.y - pq.y) * INV_NORM; dya = __fdividef(dya, 1.f + fabsf(dya));
    float dxb = (pkb.x - pq.x) * INV_NORM; dxb = __fdividef(dxb, 1.f + fabsf(dxb));
    float dyb = (pkb.y - pq.y) * INV_NORM; dyb = __fdividef(dyb, 1.f + fabsf(dyb));

    float A0[8] = {};
    float A1[8] = {};
    {
        float sa, ca, sb, cb, sda, cda, sdb, cdb;
        __sincosf(dxa * PI_F, &sa, &ca);  __sincosf(dxa * DSTEP_F, &sda, &cda);
        __sincosf(dxb * PI_F, &sb, &cb);  __sincosf(dxb * DSTEP_F, &sdb, &cdb);
#pragma unroll
        for (int k = 0; k < 16; k++) {
            float4 p0 = Pt4[2 * k],        p1 = Pt4[2 * k + 1];
            float4 q0 = Pt4[2 * (16 + k)], q1 = Pt4[2 * (16 + k) + 1];
            A0[0] += sa*p0.x + ca*q0.x;  A1[0] += sb*p0.x + cb*q0.x;
            A0[1] += sa*p0.y + ca*q0.y;  A1[1] += sb*p0.y + cb*q0.y;
            A0[2] += sa*p0.z + ca*q0.z;  A1[2] += sb*p0.z + cb*q0.z;
            A0[3] += sa*p0.w + ca*q0.w;  A1[3] += sb*p0.w + cb*q0.w;
            A0[4] += sa*p1.x + ca*q1.x;  A1[4] += sb*p1.x + cb*q1.x;
            A0[5] += sa*p1.y + ca*q1.y;  A1[5] += sb*p1.y + cb*q1.y;
            A0[6] += sa*p1.z + ca*q1.z;  A1[6] += sb*p1.z + cb*q1.z;
            A0[7] += sa*p1.w + ca*q1.w;  A1[7] += sb*p1.w + cb*q1.w;
            float ns = sa*cda + ca*sda, nc = ca*cda - sa*sda; sa = ns; ca = nc;
            ns = sb*cdb + cb*sdb; nc = cb*cdb - sb*sdb; sb = ns; cb = nc;
        }
        float4 p0 = Pt4[64], p1 = Pt4[65];
        A0[0] += dxa*p0.x; A0[1] += dxa*p0.y; A0[2] += dxa*p0.z; A0[3] += dxa*p0.w;
        A0[4] += dxa*p1.x; A0[5] += dxa*p1.y; A0[6] += dxa*p1.z; A0[7] += dxa*p1.w;
        A1[0] += dxb*p0.x; A1[1] += dxb*p0.y; A1[2] += dxb*p0.z; A1[3] += dxb*p0.w;
        A1[4] += dxb*p1.x; A1[5] += dxb*p1.y; A1[6] += dxb*p1.z; A1[7] += dxb*p1.w;
    }
    {
        float sa, ca, sb, cb, sda, cda, sdb, cdb;
        __sincosf(dya * PI_F, &sa, &ca);  __sincosf(dya * DSTEP_F, &sda, &cda);
        __sincosf(dyb * PI_F, &sb, &cb);  __sincosf(dyb * DSTEP_F, &sdb, &cdb);
#pragma unroll
        for (int k = 0; k < 16; k++) {
            float4 p0 = Pt4[2 * (33 + k)], p1 = Pt4[2 * (33 + k) + 1];
            float4 q0 = Pt4[2 * (49 + k)], q1 = Pt4[2 * (49 + k) + 1];
            A0[0] += sa*p0.x + ca*q0.x;  A1[0] += sb*p0.x + cb*q0.x;
            A0[1] += sa*p0.y + ca*q0.y;  A1[1] += sb*p0.y + cb*q0.y;
            A0[2] += sa*p0.z + ca*q0.z;  A1[2] += sb*p0.z + cb*q0.z;
            A0[3] += sa*p0.w + ca*q0.w;  A1[3] += sb*p0.w + cb*q0.w;
            A0[4] += sa*p1.x + ca*q1.x;  A1[4] += sb*p1.x + cb*q1.x;
            A0[5] += sa*p1.y + ca*q1.y;  A1[5] += sb*p1.y + cb*q1.y;
            A0[6] += sa*p1.z + ca*q1.z;  A1[6] += sb*p1.z + cb*q1.z;
            A0[7] += sa*p1.w + ca*q1.w;  A1[7] += sb*p1.w + cb*q1.w;
            float ns = sa*cda + ca*sda, nc = ca*cda - sa*sda; sa = ns; ca = nc;
            ns = sb*cdb + cb*sdb; nc = cb*cdb - sb*sdb; sb = ns; cb = nc;
        }
        float4 p0 = Pt4[130], p1 = Pt4[131];
        A0[0] += dya*p0.x; A0[1] += dya*p0.y; A0[2] += dya*p0.z; A0[3] += dya*p0.w;
        A0[4] += dya*p1.x; A0[5] += dya*p1.y; A0[6] += dya*p1.z; A0[7] += dya*p1.w;
        A1[0] += dyb*p0.x; A1[1] += dyb*p0.y; A1[2] += dyb*p0.z; A1[3] += dyb*p0.w;
        A1[4] += dyb*p1.x; A1[5] += dyb*p1.y; A1[6] += dyb*p1.z; A1[7] += dyb*p1.w;
    }

    const float* csrow = g_sc + (size_t)i * NH * NN;
#pragma unroll
    for (int h = 0; h < NH; h++) {
        s_s[h][ja] = csrow[h * NN + ja] + A0[h] * SCALE_F;
        s_s[h][jb] = csrow[h * NN + jb] + A1[h] * SCALE_F;
    }
    __syncthreads();

    const int w = tid >> 5, lane = tid & 31;
    float m = -CUDART_INF_F;
    for (int j = lane; j < NN; j += 32) m = fmaxf(m, s_s[w][j]);
#pragma unroll
    for (int o = 16; o; o >>= 1) m = fmaxf(m, __shfl_xor_sync(0xffffffffu, m, o));
    float sum = 0.f;
    for (int j = lane; j < NN; j += 32) {
        float e = __expf(s_s[w][j] - m);
        s_s[w][j] = e;
        sum += e;
    }
#pragma unroll
    for (int o = 16; o; o >>= 1) sum += __shfl_xor_sync(0xffffffffu, sum, o);
    const float inv = __fdividef(1.0f, sum);
    float* arow = g_sc + (size_t)i * NH * NN + (size_t)w * NN;
    for (int j = lane; j < NN; j += 32)
        arow[j] = s_s[w][j] * inv;
}

// ---------------- K4: attn @ V, 64x64 tile, 4x4 thread tile, split-K=2 --
__global__ void __launch_bounds__(256) av_kernel() {
    const int i0 = blockIdx.x * 64;   // 8
    const int h  = blockIdx.y;        // 8
    const int s  = blockIdx.z;        // 2
    const int kbase = s * 256;
    __shared__ float At[32][68];      // [j][i] transposed
    __shared__ float Vt[32][68];      // [j][d]
    const int tid = threadIdx.x, tx = tid & 15, ty = tid >> 4;
    const int ai = tid >> 2, ac = tid & 3;   // attn loader: row i0+ai, j = ac*4 (+16)
    const int vj = tid >> 3, vc = tid & 7;   // v loader: row kbase+vj, d = vc*4 (+32)
    const float* arow = g_sc + ((size_t)(i0 + ai) * NH + h) * NN + kbase;
    const float* vcol = g_v + h * DH;

    float4 pa0 = *(const float4*)&arow[ac * 4];
    float4 pa1 = *(const float4*)&arow[ac * 4 + 16];
    float4 pv0 = *(const float4*)&vcol[(size_t)(kbase + vj) * INNER + vc * 4];
    float4 pv1 = *(const float4*)&vcol[(size_t)(kbase + vj) * INNER + vc * 4 + 32];

    float acc[4][4] = {};
    for (int c = 0; c < 8; c++) {
        At[ac*4+0][ai] = pa0.x; At[ac*4+1][ai] = pa0.y;
        At[ac*4+2][ai] = pa0.z; At[ac*4+3][ai] = pa0.w;
        At[ac*4+16][ai] = pa1.x; At[ac*4+17][ai] = pa1.y;
        At[ac*4+18][ai] = pa1.z; At[ac*4+19][ai] = pa1.w;
        *(float4*)&Vt[vj][vc*4]      = pv0;
        *(float4*)&Vt[vj][vc*4 + 32] = pv1;
        __syncthreads();
        if (c < 7) {
            int k0 = (c + 1) * 32;
            pa0 = *(const float4*)&arow[k0 + ac * 4];
            pa1 = *(const float4*)&arow[k0 + ac * 4 + 16];
            pv0 = *(const float4*)&vcol[(size_t)(kbase + k0 + vj) * INNER + vc * 4];
            pv1 = *(const float4*)&vcol[(size_t)(kbase + k0 + vj) * INNER + vc * 4 + 32];
        }
#pragma unroll
        for (int kk = 0; kk < 32; kk++) {
            float4 a = *(const float4*)&At[kk][ty * 4];
            float4 b = *(const float4*)&Vt[kk][tx * 4];
            float av[4] = {a.x, a.y, a.z, a.w};
            float bv[4] = {b.x, b.y, b.z, b.w};
#pragma unroll
            for (int m = 0; m < 4; m++)
#pragma unroll
                for (int n = 0; n < 4; n++) acc[m][n] += av[m] * bv[n];
        }
        __syncthreads();
    }
#pragma unroll
    for (int m = 0; m < 4; m++) {
        float4 r = make_float4(acc[m][0], acc[m][1], acc[m][2], acc[m][3]);
        *(float4*)&g_ao[((size_t)s * NN + i0 + ty * 4 + m) * INNER + h * DH + tx * 4] = r;
    }
}

// ---------------- K5: out = (ao0+ao1) @ Wo + bo, 32x64 tile, 2x4 thread --
__global__ void __launch_bounds__(256) out_kernel(const float* __restrict__ Wo,
                           const float* __restrict__ bo,
                           float* __restrict__ out) {
    const int n0 = blockIdx.x * 64;   // 4
    const int i0 = blockIdx.y * 32;   // 16
    __shared__ float At[64][34];      // [k][i]
    __shared__ float Bt[64][68];      // [k][n]
    const int tid = threadIdx.x, tx = tid & 15, ty = tid >> 4;
    const int ai2 = tid >> 3, ac2 = tid & 7;   // A: row i0+ai2, k = ac2*4 (+32)
    const int bk = tid >> 2, bc = tid & 3;     // B: row bk, n = bc*4 (+16,+32,+48)
    const float* a0row = g_ao + (size_t)(i0 + ai2) * INNER;
    const float* a1row = a0row + (size_t)NN * INNER;
    const float* wrow  = Wo + n0;

    float4 pa0, pa1, pb[4];
    {
        float4 u0 = *(const float4*)&a0row[ac2 * 4];
        float4 u1 = *(const float4*)&a1row[ac2 * 4];
        pa0 = make_float4(u0.x+u1.x, u0.y+u1.y, u0.z+u1.z, u0.w+u1.w);
        u0 = *(const float4*)&a0row[ac2 * 4 + 32];
        u1 = *(const float4*)&a1row[ac2 * 4 + 32];
        pa1 = make_float4(u0.x+u1.x, u0.y+u1.y, u0.z+u1.z, u0.w+u1.w);
#pragma unroll
        for (int u = 0; u < 4; u++)
            pb[u] = *(const float4*)&wrow[(size_t)bk * DIMX + (bc + 4 * u) * 4];
    }

    float acc[2][4] = {};
    for (int c = 0; c < 8; c++) {
        At[ac2*4+0][ai2] = pa0.x; At[ac2*4+1][ai2] = pa0.y;
        At[ac2*4+2][ai2] = pa0.z; At[ac2*4+3][ai2] = pa0.w;
        At[ac2*4+32][ai2] = pa1.x; At[ac2*4+33][ai2] = pa1.y;
        At[ac2*4+34][ai2] = pa1.z; At[ac2*4+35][ai2] = pa1.w;
#pragma unroll
        for (int u = 0; u < 4; u++)
            *(float4*)&Bt[bk][(bc + 4 * u) * 4] = pb[u];
        __syncthreads();
        if (c < 7) {
            int k0 = (c + 1) * 64;
            float4 u0 = *(const float4*)&a0row[k0 + ac2 * 4];
            float4 u1 = *(const float4*)&a1row[k0 + ac2 * 4];
            pa0 = make_float4(u0.x+u1.x, u0.y+u1.y, u0.z+u1.z, u0.w+u1.w);
            u0 = *(const float4*)&a0row[k0 + ac2 * 4 + 32];
            u1 = *(const float4*)&a1row[k0 + ac2 * 4 + 32];
            pa1 = make_float4(u0.x+u1.x, u0.y+u1.y, u0.z+u1.z, u0.w+u1.w);
#pragma unroll
            for (int u = 0; u < 4; u++)
                pb[u] = *(const float4*)&wrow[(size_t)(k0 + bk) * DIMX + (bc + 4 * u) * 4];
        }
#pragma unroll
        for (int kk = 0; kk < 64; kk++) {
            float2 a = *(const float2*)&At[kk][ty * 2];
            float4 b = *(const float4*)&Bt[kk][tx * 4];
            acc[0][0] += a.x * b.x; acc[0][1] += a.x * b.y;
            acc[0][2] += a.x * b.z; acc[0][3] += a.x * b.w;
            acc[1][0] += a.y * b.x; acc[1][1] += a.y * b.y;
            acc[1][2] += a.y * b.z; acc[1][3] += a.y * b.w;
        }
        __syncthreads();
    }
    float4 bv = *(const float4*)&bo[n0 + tx * 4];
#pragma unroll
    for (int m = 0; m < 2; m++) {
        float4 r = make_float4(acc[m][0] + bv.x, acc[m][1] + bv.y,
                               acc[m][2] + bv.z, acc[m][3] + bv.w);
        *(float4*)&out[(size_t)(i0 + ty * 2 + m) * DIMX + n0 + tx * 4] = r;
    }
}

// ---------------- launch ----------------------------------------------
extern "C" void kernel_launch(void* const* d_in, const int* in_sizes, int n_in,
                              void* d_out, int out_size) {
    const float* x   = (const float*)d_in[0];
    const float* pos = (const float*)d_in[1];
    const float* Wq  = (const float*)d_in[2];
    const float* Wk  = (const float*)d_in[3];
    const float* Wv  = (const float*)d_in[4];
    const float* Wo  = (const float*)d_in[5];
    const float* bo  = (const float*)d_in[6];
    float* out = (float*)d_out;

    qkv_kernel<<<dim3(8, 8, 3), 256>>>(x, Wq, Wk, Wv);
    cs_p_kernel<<<dim3(8, 8, 9), 256>>>(Wk);
    rpe_softmax_kernel<<<512, 256>>>(pos);
    av_kernel<<<dim3(8, 8, 2), 256>>>();
    out_kernel<<<dim3(4, 16), 256>>>(Wo, bo, out);
}